// round 6
// baseline (speedup 1.0000x reference)
#include <cuda_runtime.h>

// Problem constants (fixed shapes from reference: B=16, H=W=1536)
#define H_DIM  1536
#define W_DIM  1536
#define B_DIM  16
#define HW     (H_DIM * W_DIM)      // 2359296
#define HW4    (HW / 4)             // 589824 float4 per plane
#define W4     (W_DIM / 4)          // 384 float4 per row
#define TPB    192                  // each thread handles w4 = t and t+192

// 36-bit tile masks, bit index = (r%6)*6 + (c%6)
// R_POS = (0,4)(1,0)(1,2)(2,4)(3,1)(4,3)(4,5)(5,1)
// B_POS = (0,1)(1,3)(1,5)(2,1)(3,4)(4,0)(4,2)(5,4)
#define R_MASK ((1ull<<4)|(1ull<<6)|(1ull<<8)|(1ull<<16)|(1ull<<19)|(1ull<<27)|(1ull<<29)|(1ull<<31))
#define B_MASK ((1ull<<1)|(1ull<<9)|(1ull<<11)|(1ull<<13)|(1ull<<22)|(1ull<<24)|(1ull<<26)|(1ull<<34))

static __device__ __forceinline__ float4 sel4(unsigned m, int c0,
                                              const float4& a, const float4& b)
{
    float4 o;
    o.x = ((m >> (c0 + 0)) & 1u) ? a.x : b.x;
    o.y = ((m >> (c0 + 1)) & 1u) ? a.y : b.y;
    o.z = ((m >> (c0 + 2)) & 1u) ? a.z : b.z;
    o.w = ((m >> (c0 + 3)) & 1u) ? a.w : b.w;
    return o;
}

__global__ __launch_bounds__(TPB, 8) void xflat_rgb_extract_kernel(
    const float4* __restrict__ green,   // [B,1,H,W]
    const float4* __restrict__ xtrans,  // [B,3,H,W]
    const float4* __restrict__ chroma,  // [B,2,H,W]
    float4* __restrict__ out)           // [B,3,H,W]
{
    const int t = threadIdx.x;         // 0..191
    const int h = blockIdx.x;          // 0..1535
    const int b = blockIdx.y;          // 0..15

    // Row mask patterns: 6 bits, doubled to 12 so lanes c0..c0+3 index directly
    const int r6 = h % 6;
    unsigned rrow = (unsigned)((R_MASK >> (r6 * 6)) & 63u);
    unsigned brow = (unsigned)((B_MASK >> (r6 * 6)) & 63u);
    rrow |= rrow << 6;
    brow |= brow << 6;

    // 768 = 192*4 is divisible by 6, so both halves share the same residue.
    const int c0 = (t * 4) % 6;

    const int rowOff = h * W4 + t;     // float4 units; second half at +TPB
    const int b1 = b * HW4;            // green plane base
    const int b2 = b * (2 * HW4);      // chroma base
    const int b3 = b * (3 * HW4);      // xtrans / out base

    // 10 independent 128-bit streaming loads, front-batched (MLP=10)
    const float4 xv0a = __ldcs(&xtrans[b3 + rowOff]);
    const float4 xv0b = __ldcs(&xtrans[b3 + rowOff + TPB]);
    const float4 xv2a = __ldcs(&xtrans[b3 + 2 * HW4 + rowOff]);
    const float4 xv2b = __ldcs(&xtrans[b3 + 2 * HW4 + rowOff + TPB]);
    const float4 cv0a = __ldcs(&chroma[b2 + rowOff]);
    const float4 cv0b = __ldcs(&chroma[b2 + rowOff + TPB]);
    const float4 cv1a = __ldcs(&chroma[b2 + HW4 + rowOff]);
    const float4 cv1b = __ldcs(&chroma[b2 + HW4 + rowOff + TPB]);
    const float4 gva  = __ldcs(&green [b1 + rowOff]);
    const float4 gvb  = __ldcs(&green [b1 + rowOff + TPB]);

    const float4 o0a = sel4(rrow, c0, xv0a, cv0a);
    const float4 o0b = sel4(rrow, c0, xv0b, cv0b);
    const float4 o2a = sel4(brow, c0, xv2a, cv1a);
    const float4 o2b = sel4(brow, c0, xv2b, cv1b);

    __stcs(&out[b3 + rowOff],                 o0a);
    __stcs(&out[b3 + rowOff + TPB],           o0b);
    __stcs(&out[b3 + HW4 + rowOff],           gva);
    __stcs(&out[b3 + HW4 + rowOff + TPB],     gvb);
    __stcs(&out[b3 + 2 * HW4 + rowOff],       o2a);
    __stcs(&out[b3 + 2 * HW4 + rowOff + TPB], o2b);
}

extern "C" void kernel_launch(void* const* d_in, const int* in_sizes, int n_in,
                              void* d_out, int out_size)
{
    const float4* green  = (const float4*)d_in[0];  // green_pred  [16,1,1536,1536]
    const float4* xtrans = (const float4*)d_in[1];  // xtrans      [16,3,1536,1536]
    const float4* chroma = (const float4*)d_in[2];  // chroma_pred [16,2,1536,1536]
    float4* out = (float4*)d_out;                   // [16,3,1536,1536] float32

    dim3 grid(H_DIM, B_DIM);
    dim3 block(TPB);
    xflat_rgb_extract_kernel<<<grid, block>>>(green, xtrans, chroma, out);
}